// round 6
// baseline (speedup 1.0000x reference)
#include <cuda_runtime.h>

// ---------------------------------------------------------------------------
// Inverse DTCWT qshift level, fully fused, barrier-free, row-pair streaming.
//
// Filter algebra (validated R1-R4, rel_err ~1e-7):
//   10-tap qshift synthesis reduces to 3 nonzero taps per output phase s=n&3
//   over inputs at reflect(2*(n>>2)+off).  F1 is a phase/sign permutation of F0.
//   Rows 2h,2h+1 share the same 12 subband plane values; parity flips roles.
//
// R5: 128-row strips (grid 2048 fills the 1184 CTA slots; R4's 1024 did not),
//   interior fast path (no reflect/swap, pointer-increment loads with
//   immediate offsets), RS2 folded into taps, launch_bounds(128,8).
// ---------------------------------------------------------------------------

static constexpr float A0 =  0.0351638365171441f;
static constexpr float A2 = -0.0883294244510729f;
static constexpr float A3c = 0.233890320607236f;
static constexpr float A4 =  0.760272369066126f;
static constexpr float A5 =  0.587518297723561f;
static constexpr float A7 = -0.114301837144249f;
static constexpr float RS2 = 0.70710678118654752440f;
static constexpr float SQ2 = 1.41421356237309504880f;

__constant__ int c_off[2][4][3] = {
    { { 4, 2, 0 }, { 3, 1, -1 }, { 2, 0, -2 }, { 1, -1, -3 } },
    { { 3, 1, -1 }, { 4, 2, 0 }, { 1, -1, -3 }, { 2, 0, -2 } }
};
// taps pre-scaled by RS2 (c2q scale folded in; yl path compensated by SQ2)
__constant__ float c_t0r[4][3] = {
    { A0*RS2, A2*RS2, A4*RS2 }, { A7*RS2, A5*RS2, A3c*RS2 },
    { A3c*RS2, A5*RS2, A7*RS2 }, { A4*RS2, A2*RS2, A0*RS2 }
};
__constant__ float c_t1r[4][3] = {
    { A7*RS2, A5*RS2, A3c*RS2 }, { -A0*RS2, -A2*RS2, -A4*RS2 },
    { -A4*RS2, -A2*RS2, -A0*RS2 }, { A3c*RS2, A5*RS2, A7*RS2 }
};

__device__ __forceinline__ int rf128(int x) {
    return x < 0 ? (-1 - x) : (x > 127 ? (255 - x) : x);
}

#define IW   128
#define HH2  64
#define OW   256
#define PL   4096
#define FULLM 0xffffffffu

__global__ __launch_bounds__(128, 8)
void dtcwt_inv_kernel(const float* __restrict__ Yl,
                      const float* __restrict__ Yhr,
                      const float* __restrict__ Yhi,
                      float* __restrict__ out)
{
    const int tid  = threadIdx.x;
    const int lane = tid & 31;
    const int S    = blockIdx.x >> 1;                      // 128-row strip
    const int wq   = ((blockIdx.x & 1) << 2) | (tid >> 5); // col group 0..7
    const int g    = blockIdx.y;

    const float* ylg = Yl  + (size_t)g * (IW * IW);
    const float* yhr = Yhr + (size_t)g * (6 * PL);
    const float* yhi = Yhi + (size_t)g * (6 * PL);
    float*       og  = out + (size_t)g * (OW * OW);

    // ---- per-lane constants ------------------------------------------------
    const int col = wq * 32 + lane;
    const int s   = col & 3;

    const float r00 = c_t0r[s][0], r01 = c_t0r[s][1], r02 = c_t0r[s][2];
    const float r10 = c_t1r[s][0], r11 = c_t1r[s][1], r12 = c_t1r[s][2];

    const int lb  = (lane >> 2) << 1;
    const int s00 = lb + c_off[0][s][0] + 3;
    const int s01 = lb + c_off[0][s][1] + 3;
    const int s02 = lb + c_off[0][s][2] + 3;
    const int s10 = lb + c_off[1][s][0] + 3;
    const int s11 = lb + c_off[1][s][1] + 3;
    const int s12 = lb + c_off[1][s][2] + 3;

    const int   x  = rf128(16 * wq - 3 + lane);  // staged input column
    const bool  p  = (x & 1) != 0;               // c2q column parity

    const float* ylx = ylg + x;
    const float* Rb  = yhr + (x >> 1);
    const float* Ib  = yhi + (x >> 1);

    // ---- horizontal gather (12 shuffles) for one y-row ---------------------
    auto hshuf = [&](float yl, float lh, float hl, float hh,
                     float& y1, float& y2) {
        y1 = r00 * __shfl_sync(FULLM, yl, s00)
           + r01 * __shfl_sync(FULLM, yl, s01)
           + r02 * __shfl_sync(FULLM, yl, s02)
           + r10 * __shfl_sync(FULLM, hl, s10)
           + r11 * __shfl_sync(FULLM, hl, s11)
           + r12 * __shfl_sync(FULLM, hl, s12);
        y2 = r00 * __shfl_sync(FULLM, lh, s00)
           + r01 * __shfl_sync(FULLM, lh, s01)
           + r02 * __shfl_sync(FULLM, lh, s02)
           + r10 * __shfl_sync(FULLM, hh, s10)
           + r11 * __shfl_sync(FULLM, hh, s11)
           + r12 * __shfl_sync(FULLM, hh, s12);
    };

    // ---- general row pair (handles reflection + parity swap) ---------------
    auto cpair_gen = [&](int h, float& y1a, float& y2a, float& y1b, float& y2b) {
        const int yr0 = rf128(2 * h);
        const int yr1 = rf128(2 * h + 1);
        const int hb  = (yr0 >> 1) * HH2;

        const float yl0 = ylx[yr0 * IW] * SQ2;
        const float yl1 = ylx[yr1 * IW] * SQ2;

        const float* R = Rb + hb;
        const float* I = Ib + hb;
        const float R0 = R[0],    R1 = R[PL],   R2v = R[2*PL];
        const float R3 = R[3*PL], R4 = R[4*PL], R5  = R[5*PL];
        const float I0 = I[0],    I1 = I[PL],   I2v = I[2*PL];
        const float I3 = I[3*PL], I4 = I[4*PL], I5  = I[5*PL];

        float lhA = p ? (I0  + I5) : (R0  + R5);
        float lhB = p ? (R5  - R0) : (I0  - I5);
        float hlA = p ? (I2v + I3) : (R2v + R3);
        float hlB = p ? (R3 - R2v) : (I2v - I3);
        float hhA = p ? (I1  + I4) : (R1  + R4);
        float hhB = p ? (R4  - R1) : (I1  - I4);

        if (yr0 & 1) {   // boundary reflection flips pair parity (warp-uniform)
            float t;
            t = lhA; lhA = lhB; lhB = t;
            t = hlA; hlA = hlB; hlB = t;
            t = hhA; hhA = hhB; hhB = t;
        }
        hshuf(yl0, lhA, hlA, hhA, y1a, y2a);
        hshuf(yl1, lhB, hlB, hhB, y1b, y2b);
    };

    // ---- fast interior pair: pointer-increment, immediate offsets ----------
    const int i0 = S * 32;
    const float* ylp = ylx + (size_t)(2 * (i0 + 3)) * IW;
    const float* Rp  = Rb  + (i0 + 3) * HH2;
    const float* Ip  = Ib  + (i0 + 3) * HH2;

    auto cpair_fast = [&](float& y1a, float& y2a, float& y1b, float& y2b) {
        const float yl0 = ylp[0]  * SQ2;
        const float yl1 = ylp[IW] * SQ2;
        const float R0 = Rp[0],    R1 = Rp[PL],   R2v = Rp[2*PL];
        const float R3 = Rp[3*PL], R4 = Rp[4*PL], R5  = Rp[5*PL];
        const float I0 = Ip[0],    I1 = Ip[PL],   I2v = Ip[2*PL];
        const float I3 = Ip[3*PL], I4 = Ip[4*PL], I5  = Ip[5*PL];

        const float lhA = p ? (I0  + I5) : (R0  + R5);
        const float lhB = p ? (R5  - R0) : (I0  - I5);
        const float hlA = p ? (I2v + I3) : (R2v + R3);
        const float hlB = p ? (R3 - R2v) : (I2v - I3);
        const float hhA = p ? (I1  + I4) : (R1  + R4);
        const float hhB = p ? (R4  - R1) : (I1  - I4);

        hshuf(yl0, lhA, hlA, hhA, y1a, y2a);
        hshuf(yl1, lhB, hlB, hhB, y1b, y2b);

        ylp += 2 * IW; Rp += HH2; Ip += HH2;
    };

    // ---- window: w[j] = y row (2*i0 - 4 + 2*step + j), j = 0..9 ------------
    float w1[10], w2[10];
#pragma unroll
    for (int k = 0; k < 5; ++k)
        cpair_gen(i0 - 2 + k, w1[2*k], w2[2*k], w1[2*k+1], w2[2*k+1]);

    float* op = og + (size_t)(S * 128) * OW + col;

    auto emit = [&]() {
        const float v0 = A0  * w1[8] + A2  * w1[6] + A4 * w1[4]
                       + A7  * w2[7] + A5  * w2[5] + A3c * w2[3];
        const float v1 = A7  * w1[7] + A5  * w1[5] + A3c * w1[3]
                       - A0  * w2[8] - A2  * w2[6] - A4 * w2[4];
        const float v2 = A3c * w1[6] + A5  * w1[4] + A7 * w1[2]
                       - A4  * w2[5] - A2  * w2[3] - A0 * w2[1];
        const float v3 = A4  * w1[5] + A2  * w1[3] + A0 * w1[1]
                       + A3c * w2[6] + A5  * w2[4] + A7 * w2[2];
        __stcs(op + 0 * OW, v0);
        __stcs(op + 1 * OW, v1);
        __stcs(op + 2 * OW, v2);
        __stcs(op + 3 * OW, v3);
        op += 4 * OW;
    };
    auto shift = [&]() {
#pragma unroll
        for (int j = 0; j < 8; ++j) { w1[j] = w1[j + 2]; w2[j] = w2[j + 2]; }
    };

    // steady: 31 (emit + load) + final emit.  Loads at h = i0+3+ii;
    // fast while h <= 63 (nfast = min(31, 61 - i0)).
    const int nfast = (61 - i0 < 31) ? (61 - i0) : 31;
    int ii = 0;
#pragma unroll 2
    for (; ii < nfast; ++ii) {
        emit();
        shift();
        cpair_fast(w1[8], w2[8], w1[9], w2[9]);
    }
    for (; ii < 31; ++ii) {
        emit();
        shift();
        cpair_gen(i0 + 3 + ii, w1[8], w2[8], w1[9], w2[9]);
    }
    emit();
}

extern "C" void kernel_launch(void* const* d_in, const int* in_sizes, int n_in,
                              void* d_out, int out_size)
{
    const float* Yl  = (const float*)d_in[0];
    const float* Yhr = (const float*)d_in[1];
    const float* Yhi = (const float*)d_in[2];
    float* out = (float*)d_out;

    const int n_img = in_sizes[0] / (IW * IW);   // 512 for (8,64,128,128)

    dim3 grid(4, n_img);   // x: (strip<<1)|col-half, y: image
    dtcwt_inv_kernel<<<grid, 128>>>(Yl, Yhr, Yhi, out);
}

// round 7
// speedup vs baseline: 1.7593x; 1.7593x over previous
#include <cuda_runtime.h>

// ---------------------------------------------------------------------------
// Inverse DTCWT qshift level, fully fused, barrier-free, row-pair streaming.
//
// Filter algebra (validated R1-R5, rel_err ~1e-7):
//   10-tap qshift synthesis reduces to 3 nonzero taps per output phase s=n&3
//   over inputs at reflect(2*(n>>2)+off).  F1 is a phase/sign permutation of F0.
//   Rows 2h,2h+1 share the same 12 subband plane values; parity flips roles.
//
// R6: single static cpair path (no dynamic-bound loops -- R5 showed those
//   serialize the load stream), 64-row strips (grid 4096 for occupancy),
//   FULL unroll of the 16-step window loop so shifts become register renames
//   and ptxas can batch loads across pairs (MLP).
// ---------------------------------------------------------------------------

static constexpr float A0 =  0.0351638365171441f;
static constexpr float A2 = -0.0883294244510729f;
static constexpr float A3c = 0.233890320607236f;
static constexpr float A4 =  0.760272369066126f;
static constexpr float A5 =  0.587518297723561f;
static constexpr float A7 = -0.114301837144249f;
static constexpr float RS2 = 0.70710678118654752440f;
static constexpr float SQ2 = 1.41421356237309504880f;

__constant__ int c_off[2][4][3] = {
    { { 4, 2, 0 }, { 3, 1, -1 }, { 2, 0, -2 }, { 1, -1, -3 } },
    { { 3, 1, -1 }, { 4, 2, 0 }, { 1, -1, -3 }, { 2, 0, -2 } }
};
// taps pre-scaled by RS2 (c2q scale folded in; yl path compensated by SQ2)
__constant__ float c_t0r[4][3] = {
    { A0*RS2, A2*RS2, A4*RS2 }, { A7*RS2, A5*RS2, A3c*RS2 },
    { A3c*RS2, A5*RS2, A7*RS2 }, { A4*RS2, A2*RS2, A0*RS2 }
};
__constant__ float c_t1r[4][3] = {
    { A7*RS2, A5*RS2, A3c*RS2 }, { -A0*RS2, -A2*RS2, -A4*RS2 },
    { -A4*RS2, -A2*RS2, -A0*RS2 }, { A3c*RS2, A5*RS2, A7*RS2 }
};

__device__ __forceinline__ int rf128(int x) {
    return x < 0 ? (-1 - x) : (x > 127 ? (255 - x) : x);
}

#define IW   128
#define HH2  64
#define OW   256
#define PL   4096
#define FULLM 0xffffffffu

__global__ __launch_bounds__(128, 8)
void dtcwt_inv_kernel(const float* __restrict__ Yl,
                      const float* __restrict__ Yhr,
                      const float* __restrict__ Yhi,
                      float* __restrict__ out)
{
    const int tid  = threadIdx.x;
    const int lane = tid & 31;
    const int S    = blockIdx.x >> 1;                      // 64-row strip 0..3
    const int wq   = ((blockIdx.x & 1) << 2) | (tid >> 5); // col group 0..7
    const int g    = blockIdx.y;

    const float* ylg = Yl  + (size_t)g * (IW * IW);
    const float* yhr = Yhr + (size_t)g * (6 * PL);
    const float* yhi = Yhi + (size_t)g * (6 * PL);
    float*       og  = out + (size_t)g * (OW * OW);

    // ---- per-lane constants ------------------------------------------------
    const int col = wq * 32 + lane;
    const int s   = col & 3;

    const float r00 = c_t0r[s][0], r01 = c_t0r[s][1], r02 = c_t0r[s][2];
    const float r10 = c_t1r[s][0], r11 = c_t1r[s][1], r12 = c_t1r[s][2];

    const int lb  = (lane >> 2) << 1;
    const int s00 = lb + c_off[0][s][0] + 3;
    const int s01 = lb + c_off[0][s][1] + 3;
    const int s02 = lb + c_off[0][s][2] + 3;
    const int s10 = lb + c_off[1][s][0] + 3;
    const int s11 = lb + c_off[1][s][1] + 3;
    const int s12 = lb + c_off[1][s][2] + 3;

    const int   x  = rf128(16 * wq - 3 + lane);  // staged input column
    const bool  p  = (x & 1) != 0;               // c2q column parity

    const float* ylx = ylg + x;
    const float* Rb  = yhr + (x >> 1);
    const float* Ib  = yhi + (x >> 1);

    // ---- one row pair (rows 2h, 2h+1): 14 coalesced LDG + c2q + 24 SHFL ----
    auto cpair = [&](int h, float& y1a, float& y2a, float& y1b, float& y2b) {
        const int yr0 = rf128(2 * h);
        const int yr1 = rf128(2 * h + 1);
        const int hb  = (yr0 >> 1) * HH2;

        const float yl0 = ylx[yr0 * IW] * SQ2;
        const float yl1 = ylx[yr1 * IW] * SQ2;

        const float* R = Rb + hb;
        const float* I = Ib + hb;
        const float R0 = R[0],    R1 = R[PL],   R2v = R[2*PL];
        const float R3 = R[3*PL], R4 = R[4*PL], R5  = R[5*PL];
        const float I0 = I[0],    I1 = I[PL],   I2v = I[2*PL];
        const float I3 = I[3*PL], I4 = I[4*PL], I5  = I[5*PL];

        float lhA = p ? (I0  + I5) : (R0  + R5);
        float lhB = p ? (R5  - R0) : (I0  - I5);
        float hlA = p ? (I2v + I3) : (R2v + R3);
        float hlB = p ? (R3 - R2v) : (I2v - I3);
        float hhA = p ? (I1  + I4) : (R1  + R4);
        float hhB = p ? (R4  - R1) : (I1  - I4);

        if (yr0 & 1) {   // boundary reflection flips pair parity (warp-uniform)
            float t;
            t = lhA; lhA = lhB; lhB = t;
            t = hlA; hlA = hlB; hlB = t;
            t = hhA; hhA = hhB; hhB = t;
        }

        y1a = r00 * __shfl_sync(FULLM, yl0, s00)
            + r01 * __shfl_sync(FULLM, yl0, s01)
            + r02 * __shfl_sync(FULLM, yl0, s02)
            + r10 * __shfl_sync(FULLM, hlA, s10)
            + r11 * __shfl_sync(FULLM, hlA, s11)
            + r12 * __shfl_sync(FULLM, hlA, s12);
        y2a = r00 * __shfl_sync(FULLM, lhA, s00)
            + r01 * __shfl_sync(FULLM, lhA, s01)
            + r02 * __shfl_sync(FULLM, lhA, s02)
            + r10 * __shfl_sync(FULLM, hhA, s10)
            + r11 * __shfl_sync(FULLM, hhA, s11)
            + r12 * __shfl_sync(FULLM, hhA, s12);
        y1b = r00 * __shfl_sync(FULLM, yl1, s00)
            + r01 * __shfl_sync(FULLM, yl1, s01)
            + r02 * __shfl_sync(FULLM, yl1, s02)
            + r10 * __shfl_sync(FULLM, hlB, s10)
            + r11 * __shfl_sync(FULLM, hlB, s11)
            + r12 * __shfl_sync(FULLM, hlB, s12);
        y2b = r00 * __shfl_sync(FULLM, lhB, s00)
            + r01 * __shfl_sync(FULLM, lhB, s01)
            + r02 * __shfl_sync(FULLM, lhB, s02)
            + r10 * __shfl_sync(FULLM, hhB, s10)
            + r11 * __shfl_sync(FULLM, hhB, s11)
            + r12 * __shfl_sync(FULLM, hhB, s12);
    };

    // ---- window: w[j] = y row (2*(i0+ii) - 4 + j), j = 0..9 ----------------
    const int i0 = S * 16;
    float w1[10], w2[10];
#pragma unroll
    for (int k = 0; k < 5; ++k)
        cpair(i0 - 2 + k, w1[2*k], w2[2*k], w1[2*k+1], w2[2*k+1]);

    float* op = og + (size_t)(S * 64) * OW + col;

#pragma unroll
    for (int ii = 0; ii < 16; ++ii) {
        const float v0 = A0  * w1[8] + A2  * w1[6] + A4 * w1[4]
                       + A7  * w2[7] + A5  * w2[5] + A3c * w2[3];
        const float v1 = A7  * w1[7] + A5  * w1[5] + A3c * w1[3]
                       - A0  * w2[8] - A2  * w2[6] - A4 * w2[4];
        const float v2 = A3c * w1[6] + A5  * w1[4] + A7 * w1[2]
                       - A4  * w2[5] - A2  * w2[3] - A0 * w2[1];
        const float v3 = A4  * w1[5] + A2  * w1[3] + A0 * w1[1]
                       + A3c * w2[6] + A5  * w2[4] + A7 * w2[2];

        __stcs(op + 0 * OW, v0);
        __stcs(op + 1 * OW, v1);
        __stcs(op + 2 * OW, v2);
        __stcs(op + 3 * OW, v3);
        op += 4 * OW;

        if (ii < 15) {
#pragma unroll
            for (int j = 0; j < 8; ++j) { w1[j] = w1[j + 2]; w2[j] = w2[j + 2]; }
            cpair(i0 + 3 + ii, w1[8], w2[8], w1[9], w2[9]);
        }
    }
}

extern "C" void kernel_launch(void* const* d_in, const int* in_sizes, int n_in,
                              void* d_out, int out_size)
{
    const float* Yl  = (const float*)d_in[0];
    const float* Yhr = (const float*)d_in[1];
    const float* Yhi = (const float*)d_in[2];
    float* out = (float*)d_out;

    const int n_img = in_sizes[0] / (IW * IW);   // 512 for (8,64,128,128)

    dim3 grid(8, n_img);   // x: (strip<<1)|col-half, y: image
    dtcwt_inv_kernel<<<grid, 128>>>(Yl, Yhr, Yhi, out);
}